// round 7
// baseline (speedup 1.0000x reference)
#include <cuda_runtime.h>
#include <cuda_fp16.h>
#include <cstdint>

#define B 512
#define DX 128
#define H 512

// ---------------- scratch (no allocs allowed) ----------------
__device__ float g_hx[B * H];
__device__ float g_hyb[B * H];
__device__ __half g_W2h[H * H];

// ---------------------------------------------------------------------------
// Layer 1: out[r][h] = sum_d in[r][d] * W1[h][off+d] (+ b1[h] if addb)
// ---------------------------------------------------------------------------
__global__ void gemm_h_kernel(const float* __restrict__ in,
                              const float* __restrict__ W1,
                              const float* __restrict__ b1,
                              int off, int addb) {
    __shared__ float xs[16][17];
    __shared__ float ws[16][17];
    int tx = threadIdx.x, ty = threadIdx.y;
    int r0 = blockIdx.y * 16, h0 = blockIdx.x * 16;
    float acc = 0.f;
    for (int kt = 0; kt < DX; kt += 16) {
        xs[ty][tx] = in[(r0 + ty) * DX + kt + tx];
        ws[ty][tx] = W1[(h0 + ty) * (2 * DX) + off + kt + tx];
        __syncthreads();
#pragma unroll
        for (int k = 0; k < 16; k++)
            acc = fmaf(xs[ty][k], ws[tx][k], acc);
        __syncthreads();
    }
    float bv = addb ? b1[h0 + tx] : 0.f;
    float* outp = addb ? g_hyb : g_hx;
    outp[(r0 + ty) * H + h0 + tx] = acc + bv;
}

// ---------------------------------------------------------------------------
// Convert W2 fp32 -> fp16 (single copy)
// ---------------------------------------------------------------------------
__global__ void wconv_kernel(const float* __restrict__ W2) {
    int idx = blockIdx.x * 256 + threadIdx.x;
    g_W2h[idx] = __float2half_rn(W2[idx]);
}

// ---------------------------------------------------------------------------
// helpers
// ---------------------------------------------------------------------------
__device__ __forceinline__ uint32_t smem_u32(const void* p) {
    uint32_t a;
    asm("{ .reg .u64 t; cvta.to.shared.u64 t, %1; cvt.u32.u64 %0, t; }"
        : "=r"(a) : "l"(p));
    return a;
}
__device__ __forceinline__ void ldm_x4(uint32_t& r0, uint32_t& r1,
                                       uint32_t& r2, uint32_t& r3, uint32_t a) {
    asm volatile("ldmatrix.sync.aligned.m8n8.x4.shared.b16 {%0,%1,%2,%3}, [%4];"
                 : "=r"(r0), "=r"(r1), "=r"(r2), "=r"(r3) : "r"(a));
}
__device__ __forceinline__ void mma16816(float* c, uint32_t a0, uint32_t a1,
                                         uint32_t a2, uint32_t a3,
                                         uint32_t b0, uint32_t b1) {
    asm volatile(
        "mma.sync.aligned.m16n8k16.row.col.f32.f16.f16.f32 "
        "{%0,%1,%2,%3}, {%4,%5,%6,%7}, {%8,%9}, {%0,%1,%2,%3};"
        : "+f"(c[0]), "+f"(c[1]), "+f"(c[2]), "+f"(c[3])
        : "r"(a0), "r"(a1), "r"(a2), "r"(a3), "r"(b0), "r"(b1));
}
__device__ __forceinline__ void cp16(uint32_t dst, const void* src) {
    asm volatile("cp.async.cg.shared.global [%0], [%1], 16;"
                 :: "r"(dst), "l"(src));
}

// ---------------------------------------------------------------------------
// Main fused kernel, single-pass fp16 HMMA, register-pipelined fragments.
// CTA: 512 threads (16 warps = 4 m-warps x 4 n-warps), tile m=128 (8i x 16j).
// Full A [128 x 512] fp16 cached in smem (generated once). N in 2 halves of
// 256; W tile [256n x 64k] double-buffered via cp.async. Warp tile 32m x 64n.
// Inner loop software-pipelines B fragments (double-buffered regs) so LDSM
// latency hides under the MMA block of the previous k16 step.
// ---------------------------------------------------------------------------
#define SM_A   0          // 8 chunks x [128 rows x 128B] = 128KB
#define SM_W   131072     // 2 bufs x 32KB
#define SM_BW  196608     // float2[512] = 4KB
#define SM_RED 200704     // float[4][128] = 2KB
#define SMEM_TOTAL 202752

__global__ __launch_bounds__(512, 1)
void critic_hmma(const float* __restrict__ b2,
                 const float* __restrict__ W3,
                 const float* __restrict__ b3p,
                 float* __restrict__ out) {
    extern __shared__ char smem[];
    const uint32_t sb = smem_u32(smem);
    const int t = threadIdx.x;
    const int lane = t & 31;
    const int w = t >> 5;
    const int mw = w & 3;        // m-warp: 0..3 (32 rows each)
    const int nw = w >> 2;       // n-warp: 0..3 (64 cols each)
    const int g = lane >> 2;
    const int t4 = lane & 3;
    const int i0 = blockIdx.y * 8;
    const int j0 = blockIdx.x * 16;

    for (int q = t; q < 512; q += 512)
        *(float2*)(smem + SM_BW + q * 8) = make_float2(b2[q], W3[q]);

    // ---- prologue: generate full A [128m x 512k] fp16 into smem (once)
    {
#pragma unroll 4
        for (int r = 0; r < 16; ++r) {
            int item = t + r * 512;
            int kc = item >> 10;
            int row = (item >> 3) & 127;
            int c = item & 7;
            int kg = kc * 64 + c * 8;
            const float* hxp = &g_hx[(i0 + (row >> 4)) * H + kg];
            const float* hyp = &g_hyb[(j0 + (row & 15)) * H + kg];
            float4 x0 = *(const float4*)hxp, x1 = *(const float4*)(hxp + 4);
            float4 y0 = *(const float4*)hyp, y1 = *(const float4*)(hyp + 4);
            __half2 h0 = __float22half2_rn(make_float2(
                fmaxf(x0.x + y0.x, 0.f), fmaxf(x0.y + y0.y, 0.f)));
            __half2 h1 = __float22half2_rn(make_float2(
                fmaxf(x0.z + y0.z, 0.f), fmaxf(x0.w + y0.w, 0.f)));
            __half2 h2 = __float22half2_rn(make_float2(
                fmaxf(x1.x + y1.x, 0.f), fmaxf(x1.y + y1.y, 0.f)));
            __half2 h3 = __float22half2_rn(make_float2(
                fmaxf(x1.z + y1.z, 0.f), fmaxf(x1.w + y1.w, 0.f)));
            uint32_t off = (uint32_t)(kc * 16384 + row * 128) +
                           (((uint32_t)(c * 16)) ^ ((uint32_t)((row & 7) << 4)));
            *(uint4*)(smem + SM_A + off) =
                make_uint4(*(uint32_t*)&h0, *(uint32_t*)&h1,
                           *(uint32_t*)&h2, *(uint32_t*)&h3);
        }
    }

    auto produceW = [&](int nt, int kc, int buf) {
#pragma unroll
        for (int r = 0; r < 4; ++r) {
            int item = t + r * 512;
            int n = item >> 3;
            int c = item & 7;
            const __half* src = &g_W2h[(nt * 256 + n) * H + kc * 64 + c * 8];
            uint32_t off = (uint32_t)(buf * 32768 + n * 128) +
                           (((uint32_t)(c * 16)) ^ ((uint32_t)((n & 7) << 4)));
            cp16(sb + SM_W + off, src);
        }
        asm volatile("cp.async.commit_group;" ::: "memory");
    };

    // ldmatrix A lane mapping (warp covers rows mw*32 .. +32)
    const int a_row_l = lane & 15;
    const int a_kh = lane >> 4;
    uint32_t a_base[2], a_cs[2];
#pragma unroll
    for (int tm = 0; tm < 2; tm++) {
        int row = mw * 32 + tm * 16 + a_row_l;
        a_base[tm] = sb + SM_A + row * 128;
        a_cs[tm] = (uint32_t)((row & 7) << 4) ^ (uint32_t)(a_kh * 16);
    }
    // ldmatrix B lane mapping (x4 covers 16 n x 16 k); p = 0..3 -> 64 n
    const int b_n_l = ((lane >> 4) << 3) + (lane & 7);
    const int b_kh = (lane >> 3) & 1;
    uint32_t b_off[4], b_cs[4];
#pragma unroll
    for (int p = 0; p < 4; p++) {
        int n = nw * 64 + p * 16 + b_n_l;
        b_off[p] = (uint32_t)(n * 128);
        b_cs[p] = (uint32_t)((n & 7) << 4) ^ (uint32_t)(b_kh * 16);
    }

    float pm[4];
#pragma unroll
    for (int q = 0; q < 4; q++) pm[q] = 0.f;

    float acc[2][8][4];
#pragma unroll
    for (int a = 0; a < 2; a++)
#pragma unroll
        for (int b = 0; b < 8; b++)
#pragma unroll
            for (int c = 0; c < 4; c++) acc[a][b][c] = 0.f;

    produceW(0, 0, 0);

    uint32_t bc[4][4], bn[4][4];   // B fragment double buffer (registers)

    for (int s = 0; s < 16; ++s) {
        const int nt = s >> 3, kc = s & 7, buf = s & 1;
        asm volatile("cp.async.wait_group 0;" ::: "memory");
        __syncthreads();
        if (s + 1 < 16) produceW((s + 1) >> 3, (s + 1) & 7, buf ^ 1);

        const uint32_t akc = (uint32_t)(kc * 16384);
        const uint32_t wbase = sb + SM_W + (uint32_t)(buf * 32768);

        // preload B fragments for ks=0
#pragma unroll
        for (int p = 0; p < 4; p++)
            ldm_x4(bc[p][0], bc[p][1], bc[p][2], bc[p][3],
                   wbase + b_off[p] + ((uint32_t)0 ^ b_cs[p]));

#pragma unroll
        for (int ks = 0; ks < 4; ks++) {
            // A fragments for this ks (JIT, both halves hoisted)
            uint32_t a0[4], a1[4];
            ldm_x4(a0[0], a0[1], a0[2], a0[3],
                   a_base[0] + akc + ((uint32_t)(ks * 32) ^ a_cs[0]));
            ldm_x4(a1[0], a1[1], a1[2], a1[3],
                   a_base[1] + akc + ((uint32_t)(ks * 32) ^ a_cs[1]));
            // issue next-ks B fragment loads before the MMA block
            if (ks < 3) {
#pragma unroll
                for (int p = 0; p < 4; p++)
                    ldm_x4(bn[p][0], bn[p][1], bn[p][2], bn[p][3],
                           wbase + b_off[p] +
                               ((uint32_t)((ks + 1) * 32) ^ b_cs[p]));
            }
#pragma unroll
            for (int tn = 0; tn < 8; tn++)
                mma16816(acc[0][tn], a0[0], a0[1], a0[2], a0[3],
                         bc[tn >> 1][(tn & 1) * 2], bc[tn >> 1][(tn & 1) * 2 + 1]);
#pragma unroll
            for (int tn = 0; tn < 8; tn++)
                mma16816(acc[1][tn], a1[0], a1[1], a1[2], a1[3],
                         bc[tn >> 1][(tn & 1) * 2], bc[tn >> 1][(tn & 1) * 2 + 1]);
            // rotate B buffers
            if (ks < 3) {
#pragma unroll
                for (int p = 0; p < 4; p++)
#pragma unroll
                    for (int q = 0; q < 4; q++) bc[p][q] = bn[p][q];
            }
        }

        if (kc == 7) {
            // ---- fold this 256-n half: relu(D + b2) . W3 into pm
#pragma unroll
            for (int tm = 0; tm < 2; tm++)
#pragma unroll
                for (int tn = 0; tn < 8; tn++) {
                    int n_g = nt * 256 + nw * 64 + tn * 8 + 2 * t4;
                    float2 bw0 = *(const float2*)(smem + SM_BW + n_g * 8);
                    float2 bw1 = *(const float2*)(smem + SM_BW + (n_g + 1) * 8);
                    pm[tm * 2] = fmaf(fmaxf(acc[tm][tn][0] + bw0.x, 0.f), bw0.y,
                                      pm[tm * 2]);
                    pm[tm * 2] = fmaf(fmaxf(acc[tm][tn][1] + bw1.x, 0.f), bw1.y,
                                      pm[tm * 2]);
                    pm[tm * 2 + 1] = fmaf(fmaxf(acc[tm][tn][2] + bw0.x, 0.f),
                                          bw0.y, pm[tm * 2 + 1]);
                    pm[tm * 2 + 1] = fmaf(fmaxf(acc[tm][tn][3] + bw1.x, 0.f),
                                          bw1.y, pm[tm * 2 + 1]);
                    acc[tm][tn][0] = 0.f;
                    acc[tm][tn][1] = 0.f;
                    acc[tm][tn][2] = 0.f;
                    acc[tm][tn][3] = 0.f;
                }
        }
    }

    // ---- reduce pm across the 4 lanes of each row group
#pragma unroll
    for (int q = 0; q < 4; q++) {
        pm[q] += __shfl_xor_sync(0xffffffffu, pm[q], 1);
        pm[q] += __shfl_xor_sync(0xffffffffu, pm[q], 2);
    }
    __syncthreads();
    if (t4 == 0) {
        float* red = (float*)(smem + SM_RED);
#pragma unroll
        for (int tm = 0; tm < 2; tm++) {
            red[nw * 128 + mw * 32 + tm * 16 + g] = pm[tm * 2];
            red[nw * 128 + mw * 32 + tm * 16 + 8 + g] = pm[tm * 2 + 1];
        }
    }
    __syncthreads();
    if (t < 128) {
        const float* red = (const float*)(smem + SM_RED);
        float s = red[t] + red[128 + t] + red[256 + t] + red[384 + t] + b3p[0];
        out[(i0 + (t >> 4)) * B + j0 + (t & 15)] = s;
    }
}

// ---------------------------------------------------------------------------
extern "C" void kernel_launch(void* const* d_in, const int* in_sizes, int n_in,
                              void* d_out, int out_size) {
    const float* x  = (const float*)d_in[0];
    const float* y  = (const float*)d_in[1];
    const float* W1 = (const float*)d_in[2];
    const float* b1 = (const float*)d_in[3];
    const float* W2 = (const float*)d_in[4];
    const float* b2 = (const float*)d_in[5];
    const float* W3 = (const float*)d_in[6];
    const float* b3 = (const float*)d_in[7];
    float* out = (float*)d_out;

    cudaFuncSetAttribute(critic_hmma, cudaFuncAttributeMaxDynamicSharedMemorySize,
                         SMEM_TOTAL);

    dim3 gblk(16, 16);
    dim3 ggrd(H / 16, B / 16);
    gemm_h_kernel<<<ggrd, gblk>>>(x, W1, b1, 0, 0);    // -> g_hx
    gemm_h_kernel<<<ggrd, gblk>>>(y, W1, b1, DX, 1);   // -> g_hyb (+b1)
    wconv_kernel<<<H * H / 256, 256>>>(W2);            // -> g_W2h

    critic_hmma<<<dim3(B / 16, B / 8), 512, SMEM_TOTAL>>>(b2, W3, b3, out);
}

// round 10
// speedup vs baseline: 1.0592x; 1.0592x over previous
#include <cuda_runtime.h>
#include <cuda_fp16.h>
#include <cstdint>

#define B 512
#define DX 128
#define H 512

// ---------------- scratch (no allocs allowed) ----------------
__device__ float g_hx[B * H];
__device__ float g_hyb[B * H];
__device__ __half g_W2h[H * H];

// ---------------------------------------------------------------------------
// Layer 1: out[r][h] = sum_d in[r][d] * W1[h][off+d] (+ b1[h] if addb)
// ---------------------------------------------------------------------------
__global__ void gemm_h_kernel(const float* __restrict__ in,
                              const float* __restrict__ W1,
                              const float* __restrict__ b1,
                              int off, int addb) {
    __shared__ float xs[16][17];
    __shared__ float ws[16][17];
    int tx = threadIdx.x, ty = threadIdx.y;
    int r0 = blockIdx.y * 16, h0 = blockIdx.x * 16;
    float acc = 0.f;
    for (int kt = 0; kt < DX; kt += 16) {
        xs[ty][tx] = in[(r0 + ty) * DX + kt + tx];
        ws[ty][tx] = W1[(h0 + ty) * (2 * DX) + off + kt + tx];
        __syncthreads();
#pragma unroll
        for (int k = 0; k < 16; k++)
            acc = fmaf(xs[ty][k], ws[tx][k], acc);
        __syncthreads();
    }
    float bv = addb ? b1[h0 + tx] : 0.f;
    float* outp = addb ? g_hyb : g_hx;
    outp[(r0 + ty) * H + h0 + tx] = acc + bv;
}

// ---------------------------------------------------------------------------
// Convert W2 fp32 -> fp16 (single copy)
// ---------------------------------------------------------------------------
__global__ void wconv_kernel(const float* __restrict__ W2) {
    int idx = blockIdx.x * 256 + threadIdx.x;
    g_W2h[idx] = __float2half_rn(W2[idx]);
}

// ---------------------------------------------------------------------------
// helpers
// ---------------------------------------------------------------------------
__device__ __forceinline__ uint32_t smem_u32(const void* p) {
    uint32_t a;
    asm("{ .reg .u64 t; cvta.to.shared.u64 t, %1; cvt.u32.u64 %0, t; }"
        : "=r"(a) : "l"(p));
    return a;
}
__device__ __forceinline__ void ldm_x4(uint32_t& r0, uint32_t& r1,
                                       uint32_t& r2, uint32_t& r3, uint32_t a) {
    asm volatile("ldmatrix.sync.aligned.m8n8.x4.shared.b16 {%0,%1,%2,%3}, [%4];"
                 : "=r"(r0), "=r"(r1), "=r"(r2), "=r"(r3) : "r"(a));
}
__device__ __forceinline__ void mma16816(float* c, uint32_t a0, uint32_t a1,
                                         uint32_t a2, uint32_t a3,
                                         uint32_t b0, uint32_t b1) {
    asm volatile(
        "mma.sync.aligned.m16n8k16.row.col.f32.f16.f16.f32 "
        "{%0,%1,%2,%3}, {%4,%5,%6,%7}, {%8,%9}, {%0,%1,%2,%3};"
        : "+f"(c[0]), "+f"(c[1]), "+f"(c[2]), "+f"(c[3])
        : "r"(a0), "r"(a1), "r"(a2), "r"(a3), "r"(b0), "r"(b1));
}
__device__ __forceinline__ void cp16(uint32_t dst, const void* src) {
    asm volatile("cp.async.cg.shared.global [%0], [%1], 16;"
                 :: "r"(dst), "l"(src));
}
__device__ __forceinline__ void mbar_init(uint32_t a, uint32_t cnt) {
    asm volatile("mbarrier.init.shared.b64 [%0], %1;" :: "r"(a), "r"(cnt)
                 : "memory");
}
__device__ __forceinline__ void mbar_arrive(uint32_t a) {
    asm volatile("mbarrier.arrive.shared.b64 _, [%0];" :: "r"(a) : "memory");
}
// .noinc is load-bearing: without it the arrive INCREMENTS the expected count
// (self-balancing) and a 512-count barrier never completes (R8 hang).
__device__ __forceinline__ void cp_async_mbar_arrive(uint32_t a) {
    asm volatile("cp.async.mbarrier.arrive.noinc.shared.b64 [%0];" :: "r"(a)
                 : "memory");
}
__device__ __forceinline__ void mbar_wait(uint32_t a, uint32_t parity) {
    asm volatile(
        "{\n\t.reg .pred P;\n\t"
        "WL_%=:\n\t"
        "mbarrier.try_wait.parity.shared.b64 P, [%0], %1, 0x989680;\n\t"
        "@P bra.uni WD_%=;\n\t"
        "bra.uni WL_%=;\n\t"
        "WD_%=:\n\t}"
        :: "r"(a), "r"(parity) : "memory");
}

// ---------------------------------------------------------------------------
// Main fused kernel, single-pass fp16 HMMA, mbarrier free-running pipeline.
// CTA: 512 threads (16 warps = 4 m-warps x 4 n-warps), m-tile 128 (8i x 16j).
// Full A [128 x 512] fp16 cached in smem (generated once).
// 32 stages: nt 0..3 (128-n quarters) x kc 0..7 (64-k chunks).
// W stage tile = 128n x 64k = 16KB, 4-deep ring (geometry MATCHES the ring —
// R9's illegal access was a 32KB stage written into a 16KB buffer).
// No __syncthreads in the mainloop: FULL[b]/EMPTY[b] mbarriers (count 512),
// producer runs 3 stages ahead of consumption.
// Warp tile 32m x 32n -> 32 fp32 acc/thread (~80 regs: scheduling headroom).
// ---------------------------------------------------------------------------
#define SM_A    0          // 8 chunks x [128 rows x 128B] = 128KB
#define SM_W    131072     // 4 bufs x 16KB = 64KB
#define SM_BW   196608     // float2[512] = 4KB
#define SM_RED  200704     // float[4][128] = 2KB
#define SM_MBAR 202752     // full[4], empty[4] = 64B
#define SMEM_TOTAL 202816

__global__ __launch_bounds__(512, 1)
void critic_hmma(const float* __restrict__ b2,
                 const float* __restrict__ W3,
                 const float* __restrict__ b3p,
                 float* __restrict__ out) {
    extern __shared__ char smem[];
    const uint32_t sb = smem_u32(smem);
    const int t = threadIdx.x;
    const int lane = t & 31;
    const int w = t >> 5;
    const int mw = w & 3;        // m-warp: 0..3 (32 rows each)
    const int nw = w >> 2;       // n-warp: 0..3 (32 cols each within stage)
    const int g = lane >> 2;
    const int t4 = lane & 3;
    const int i0 = blockIdx.y * 8;
    const int j0 = blockIdx.x * 16;

    const uint32_t FULL = sb + SM_MBAR;         // full[b] = FULL + b*8
    const uint32_t EMPTY = sb + SM_MBAR + 32;   // empty[b] = EMPTY + b*8

    if (t == 0) {
#pragma unroll
        for (int b = 0; b < 4; b++) {
            mbar_init(FULL + b * 8, 512);
            mbar_init(EMPTY + b * 8, 512);
        }
    }

    for (int q = t; q < 512; q += 512)
        *(float2*)(smem + SM_BW + q * 8) = make_float2(b2[q], W3[q]);

    // ---- prologue: generate full A [128m x 512k] fp16 into smem (once)
    {
#pragma unroll 4
        for (int r = 0; r < 16; ++r) {
            int item = t + r * 512;
            int kc = item >> 10;
            int row = (item >> 3) & 127;
            int c = item & 7;
            int kg = kc * 64 + c * 8;
            const float* hxp = &g_hx[(i0 + (row >> 4)) * H + kg];
            const float* hyp = &g_hyb[(j0 + (row & 15)) * H + kg];
            float4 x0 = *(const float4*)hxp, x1 = *(const float4*)(hxp + 4);
            float4 y0 = *(const float4*)hyp, y1 = *(const float4*)(hyp + 4);
            __half2 h0 = __float22half2_rn(make_float2(
                fmaxf(x0.x + y0.x, 0.f), fmaxf(x0.y + y0.y, 0.f)));
            __half2 h1 = __float22half2_rn(make_float2(
                fmaxf(x0.z + y0.z, 0.f), fmaxf(x0.w + y0.w, 0.f)));
            __half2 h2 = __float22half2_rn(make_float2(
                fmaxf(x1.x + y1.x, 0.f), fmaxf(x1.y + y1.y, 0.f)));
            __half2 h3 = __float22half2_rn(make_float2(
                fmaxf(x1.z + y1.z, 0.f), fmaxf(x1.w + y1.w, 0.f)));
            uint32_t off = (uint32_t)(kc * 16384 + row * 128) +
                           (((uint32_t)(c * 16)) ^ ((uint32_t)((row & 7) << 4)));
            *(uint4*)(smem + SM_A + off) =
                make_uint4(*(uint32_t*)&h0, *(uint32_t*)&h1,
                           *(uint32_t*)&h2, *(uint32_t*)&h3);
        }
    }
    __syncthreads();   // covers mbar init + A tile + BW preload

    // W producer: stage sp -> nt = sp>>3, kc = sp&7, buf = sp&3
    // Stage tile = 128 n-rows x 64 k (16KB): items = 128*8 c16 = 1024,
    // 512 threads x 2 reps. Max offset = buf*16K + 127*128 + 127 < 64KB.
    auto produceW = [&](int sp) {
        const int nt = sp >> 3, kc = sp & 7, buf = sp & 3;
#pragma unroll
        for (int r = 0; r < 2; ++r) {
            int item = t + r * 512;
            int n = item >> 3;          // 0..127 (local n within stage)
            int c = item & 7;
            const __half* src = &g_W2h[(nt * 128 + n) * H + kc * 64 + c * 8];
            uint32_t off = (uint32_t)(buf * 16384 + n * 128) +
                           (((uint32_t)(c * 16)) ^ ((uint32_t)((n & 7) << 4)));
            cp16(sb + SM_W + off, src);
        }
        cp_async_mbar_arrive(FULL + buf * 8);
    };

    // ldmatrix A lane mapping (warp covers rows mw*32 .. +32)
    const int a_row_l = lane & 15;
    const int a_kh = lane >> 4;
    uint32_t a_base[2], a_cs[2];
#pragma unroll
    for (int tm = 0; tm < 2; tm++) {
        int row = mw * 32 + tm * 16 + a_row_l;
        a_base[tm] = sb + SM_A + row * 128;
        a_cs[tm] = (uint32_t)((row & 7) << 4) ^ (uint32_t)(a_kh * 16);
    }
    // ldmatrix B lane mapping (x4 covers 16 n x 16 k); p = 0..1 -> 32 local n
    const int b_n_l = ((lane >> 4) << 3) + (lane & 7);
    const int b_kh = (lane >> 3) & 1;
    uint32_t b_off[2], b_cs[2];
#pragma unroll
    for (int p = 0; p < 2; p++) {
        int n = nw * 32 + p * 16 + b_n_l;   // local n within 128-n stage
        b_off[p] = (uint32_t)(n * 128);
        b_cs[p] = (uint32_t)((n & 7) << 4) ^ (uint32_t)(b_kh * 16);
    }

    float pm[4];
#pragma unroll
    for (int q = 0; q < 4; q++) pm[q] = 0.f;

    float acc[2][4][4];
#pragma unroll
    for (int a = 0; a < 2; a++)
#pragma unroll
        for (int b = 0; b < 4; b++)
#pragma unroll
            for (int c = 0; c < 4; c++) acc[a][b][c] = 0.f;

    // prologue: fill stages 0..2
    produceW(0);
    produceW(1);
    produceW(2);

    for (int s = 0; s < 32; ++s) {
        const int nt = s >> 3, kc = s & 7, buf = s & 3;

        mbar_wait(FULL + buf * 8, (uint32_t)((s >> 2) & 1));

        const uint32_t akc = (uint32_t)(kc * 16384);
        const uint32_t wbase = sb + SM_W + (uint32_t)(buf * 16384);
#pragma unroll
        for (int ks = 0; ks < 4; ks++) {
            uint32_t af[2][4];
#pragma unroll
            for (int tm = 0; tm < 2; tm++)
                ldm_x4(af[tm][0], af[tm][1], af[tm][2], af[tm][3],
                       a_base[tm] + akc + ((uint32_t)(ks * 32) ^ a_cs[tm]));
            uint32_t bf[2][4];
#pragma unroll
            for (int p = 0; p < 2; p++)
                ldm_x4(bf[p][0], bf[p][1], bf[p][2], bf[p][3],
                       wbase + b_off[p] + ((uint32_t)(ks * 32) ^ b_cs[p]));
#pragma unroll
            for (int tm = 0; tm < 2; tm++)
#pragma unroll
                for (int tn = 0; tn < 4; tn++)
                    mma16816(acc[tm][tn], af[tm][0], af[tm][1], af[tm][2],
                             af[tm][3], bf[tn >> 1][(tn & 1) * 2],
                             bf[tn >> 1][(tn & 1) * 2 + 1]);
        }

        if (kc == 7) {
            // ---- fold this 128-n quarter: relu(D + b2) . W3 into pm
#pragma unroll
            for (int tm = 0; tm < 2; tm++)
#pragma unroll
                for (int tn = 0; tn < 4; tn++) {
                    int n_g = nt * 128 + nw * 32 + tn * 8 + 2 * t4;
                    float2 bw0 = *(const float2*)(smem + SM_BW + n_g * 8);
                    float2 bw1 = *(const float2*)(smem + SM_BW + (n_g + 1) * 8);
                    pm[tm * 2] = fmaf(fmaxf(acc[tm][tn][0] + bw0.x, 0.f), bw0.y,
                                      pm[tm * 2]);
                    pm[tm * 2] = fmaf(fmaxf(acc[tm][tn][1] + bw1.x, 0.f), bw1.y,
                                      pm[tm * 2]);
                    pm[tm * 2 + 1] = fmaf(fmaxf(acc[tm][tn][2] + bw0.x, 0.f),
                                          bw0.y, pm[tm * 2 + 1]);
                    pm[tm * 2 + 1] = fmaf(fmaxf(acc[tm][tn][3] + bw1.x, 0.f),
                                          bw1.y, pm[tm * 2 + 1]);
                    acc[tm][tn][0] = 0.f;
                    acc[tm][tn][1] = 0.f;
                    acc[tm][tn][2] = 0.f;
                    acc[tm][tn][3] = 0.f;
                }
        }

        // this warp is done reading buf
        mbar_arrive(EMPTY + buf * 8);

        // produce stage s+3 (ring-4: writer of s+3 needs consumers of s-1 done)
        const int sp = s + 3;
        if (sp < 32) {
            const int pb = sp & 3;
            if (sp >= 4)
                mbar_wait(EMPTY + pb * 8, (uint32_t)(((sp >> 2) - 1) & 1));
            produceW(sp);
        }
    }

    // ---- reduce pm across the 4 lanes of each row group
#pragma unroll
    for (int q = 0; q < 4; q++) {
        pm[q] += __shfl_xor_sync(0xffffffffu, pm[q], 1);
        pm[q] += __shfl_xor_sync(0xffffffffu, pm[q], 2);
    }
    __syncthreads();
    if (t4 == 0) {
        float* red = (float*)(smem + SM_RED);
#pragma unroll
        for (int tm = 0; tm < 2; tm++) {
            red[nw * 128 + mw * 32 + tm * 16 + g] = pm[tm * 2];
            red[nw * 128 + mw * 32 + tm * 16 + 8 + g] = pm[tm * 2 + 1];
        }
    }
    __syncthreads();
    if (t < 128) {
        const float* red = (const float*)(smem + SM_RED);
        float s = red[t] + red[128 + t] + red[256 + t] + red[384 + t] + b3p[0];
        out[(i0 + (t >> 4)) * B + j0 + (t & 15)] = s;
    }
}

// ---------------------------------------------------------------------------
extern "C" void kernel_launch(void* const* d_in, const int* in_sizes, int n_in,
                              void* d_out, int out_size) {
    const float* x  = (const float*)d_in[0];
    const float* y  = (const float*)d_in[1];
    const float* W1 = (const float*)d_in[2];
    const float* b1 = (const float*)d_in[3];
    const float* W2 = (const float*)d_in[4];
    const float* b2 = (const float*)d_in[5];
    const float* W3 = (const float*)d_in[6];
    const float* b3 = (const float*)d_in[7];
    float* out = (float*)d_out;

    cudaFuncSetAttribute(critic_hmma, cudaFuncAttributeMaxDynamicSharedMemorySize,
                         SMEM_TOTAL);

    dim3 gblk(16, 16);
    dim3 ggrd(H / 16, B / 16);
    gemm_h_kernel<<<ggrd, gblk>>>(x, W1, b1, 0, 0);    // -> g_hx
    gemm_h_kernel<<<ggrd, gblk>>>(y, W1, b1, DX, 1);   // -> g_hyb (+b1)
    wconv_kernel<<<H * H / 256, 256>>>(W2);            // -> g_W2h

    critic_hmma<<<dim3(B / 16, B / 8), 512, SMEM_TOTAL>>>(b2, W3, b3, out);
}